// round 17
// baseline (speedup 1.0000x reference)
#include <cuda_runtime.h>
#include <cstdint>

// ----------------------------------------------------------------------------
// ProposalLayer (RPN): decode anchors -> top-6000 (stable) -> greedy NMS -> 300
// H=128, W=192, A=9, STRIDE=16, PRE_NMS=6000, POST_NMS=300, THRESH=0.7
// 5 graph nodes: decode(+hist16), pick16(+hist reset), compact,
// rank_scatter(+re-decode gather), chunked greedy NMS (512 thr, ~9KB smem).
// All state self-cleaning across graph replays (no reset node).
// ----------------------------------------------------------------------------

#define HH 128
#define WW 192
#define HWSZ (HH * WW)          // 24576
#define NA 9
#define NTOT (NA * HWSZ)        // 221184
#define PRE_NMS 6000
#define POST_NMS 300
#define SEL_CAP 12288
#define COLB 94                 // ceil(6000/64)

typedef unsigned long long u64;
typedef unsigned int u32;

// Anchor widths/heights (x2-x1+1); all anchor centers are at (8,8) + 16*(w,h).
__constant__ float c_aw[NA] = {184.f, 368.f, 736.f, 128.f, 256.f, 512.f, 88.f, 176.f, 352.f};
__constant__ float c_ah[NA] = {96.f, 192.f, 384.f, 128.f, 256.f, 512.f, 176.f, 352.f, 704.f};

// ------------------------------- device state -------------------------------
__device__ u32 g_scf[NTOT];                      // order-preserving score keys
__device__ u64 g_sel[SEL_CAP];                   // selected keys (unsorted)
__device__ int g_selcnt;                         // zeroed by pick16 each round
__device__ u32 g_hist16[65536];                  // zeroed by pick16 each round
__device__ u32 g_thresh;
__device__ float4 g_tboxes[PRE_NMS];             // top-6000 boxes, sorted order
__device__ u64 g_vbits[COLB];                    // zeroed by nms each round

// Shared decode routine (bit-identical in decode_kernel and rank_scatter).
__device__ __forceinline__ float4 decode_box(const float* __restrict__ deltas,
                                             const float* __restrict__ iminfo,
                                             int a, int pix, int wi, int hi) {
    float dx = deltas[(4 * a + 0) * HWSZ + pix];
    float dy = deltas[(4 * a + 1) * HWSZ + pix];
    float dw = deltas[(4 * a + 2) * HWSZ + pix];
    float dh = deltas[(4 * a + 3) * HWSZ + pix];
    dw = fminf(fmaxf(dw, -10.f), 10.f);
    dh = fminf(fmaxf(dh, -10.f), 10.f);

    float AW = c_aw[a], AH = c_ah[a];
    float cx = dx * AW + (8.f + 16.f * (float)wi);
    float cy = dy * AH + (8.f + 16.f * (float)hi);
    float pw = __expf(dw) * AW;
    float ph = __expf(dh) * AH;
    float x1 = cx - 0.5f * pw, x2 = cx + 0.5f * pw;
    float y1 = cy - 0.5f * ph, y2 = cy + 0.5f * ph;

    float maxx = iminfo[1] - 1.0f;
    float maxy = iminfo[0] - 1.0f;
    x1 = fminf(fmaxf(x1, 0.f), maxx);
    x2 = fminf(fmaxf(x2, 0.f), maxx);
    y1 = fminf(fmaxf(y1, 0.f), maxy);
    y2 = fminf(fmaxf(y2, 0.f), maxy);
    return make_float4(x1, y1, x2, y2);
}

// ------------------------------- kernels ------------------------------------

// Build score keys (validity folded in) + 16-bit-bucket global histogram.
// Boxes are NOT materialized here (re-decoded later for the ~12K selected).
__global__ void decode_kernel(const float* __restrict__ scores,
                              const float* __restrict__ deltas,
                              const float* __restrict__ iminfo) {
    int t = blockIdx.x * blockDim.x + threadIdx.x;
    if (t >= NTOT) return;
    int a = t / HWSZ;
    int pix = t - a * HWSZ;
    int wi = pix % WW;
    int hi = pix / WW;

    float sc = scores[(NA + a) * HWSZ + pix];
    float4 b = decode_box(deltas, iminfo, a, pix, wi, hi);

    float minsz = 16.f * iminfo[2];
    bool valid = (b.z - b.x + 1.0f >= minsz) && (b.w - b.y + 1.0f >= minsz);

    int i = pix * NA + a;  // reference flat ordering: ((h*W+w)*A + a)
    u32 u;
    if (valid) {
        u = __float_as_uint(sc);
        u = (u & 0x80000000u) ? ~u : (u | 0x80000000u);
    } else {
        u = 0x007FFFFFu;  // flip(-inf)
    }
    g_scf[i] = u;
    atomicAdd(&g_hist16[u >> 16], 1u);
}

// Pick 16-bit threshold from 65536-bin histogram; then zero the histogram
// (self-cleaning for the next graph replay) and reset g_selcnt.
__global__ void pick16_kernel() {
    __shared__ u32 ssum[1024];
    int t = threadIdx.x;
    int hi = 65535 - (t << 6);  // descending chunk of 64 bins
    u32 s = 0;
    #pragma unroll 8
    for (int k = 0; k < 64; k++) s += g_hist16[hi - k];
    ssum[t] = s;
    __syncthreads();
    for (int off = 1; off < 1024; off <<= 1) {
        u32 add = (t >= off) ? ssum[t - off] : 0u;
        __syncthreads();
        ssum[t] += add;
        __syncthreads();
    }
    u32 incl = ssum[t];
    u32 before = (t > 0) ? ssum[t - 1] : 0u;
    if (before < (u32)PRE_NMS && incl >= (u32)PRE_NMS) {
        u32 c = before;
        for (int k = 0; k < 64; k++) {
            u32 hb = g_hist16[hi - k];
            if (c + hb >= (u32)PRE_NMS) { g_thresh = (u32)(hi - k) << 16; break; }
            c += hb;
        }
    }
    __syncthreads();          // all reads of g_hist16 done
    #pragma unroll 8
    for (int k = 0; k < 64; k++) g_hist16[hi - k] = 0u;
    if (t == 0) g_selcnt = 0;
}

// Vectorized compaction: uint4 key loads, 4 keys per thread.
__global__ void compact_kernel() {
    int t = blockIdx.x * blockDim.x + threadIdx.x;   // NTOT/4 threads
    if (t >= NTOT / 4) return;
    u32 th = g_thresh;
    uint4 v = ((const uint4*)g_scf)[t];
    int i0 = t * 4;
    #pragma unroll
    for (int k = 0; k < 4; k++) {
        u32 vk = (k == 0) ? v.x : (k == 1) ? v.y : (k == 2) ? v.z : v.w;
        if (vk >= th) {
            int p = atomicAdd(&g_selcnt, 1);
            if (p < SEL_CAP)
                g_sel[p] = ((u64)vk << 32) | (u32)(~(u32)(i0 + k));
        }
    }
}

// Rank-and-scatter: rank(p) = #{keys > key(p)} (keys unique: ~idx embedded,
// lower idx wins ties like jax top_k). Re-decodes the selected boxes from raw
// deltas (bit-identical to decode_kernel) and scatters top-6000 into sorted
// order + validity bitmask.
__global__ void rank_scatter_kernel(const float* __restrict__ deltas,
                                    const float* __restrict__ iminfo) {
    __shared__ u64 tile[2048];
    int cnt = g_selcnt;
    if (cnt > SEL_CAP) cnt = SEL_CAP;
    int p = blockIdx.x * 256 + threadIdx.x;
    u64 mykey = (p < cnt) ? g_sel[p] : 0ull;
    int rank = 0;
    for (int base = 0; base < cnt; base += 2048) {
        int m = min(2048, cnt - base);
        __syncthreads();
        for (int i = threadIdx.x; i < m; i += 256) tile[i] = g_sel[base + i];
        __syncthreads();
        if (p < cnt) {
            int i = 0;
            for (; i + 4 <= m; i += 4) {
                rank += (tile[i] > mykey) + (tile[i+1] > mykey)
                      + (tile[i+2] > mykey) + (tile[i+3] > mykey);
            }
            for (; i < m; i++) rank += (tile[i] > mykey);
        }
    }
    if (p < cnt && rank < PRE_NMS) {
        u32 idx = ~(u32)mykey;
        int a = idx % NA;
        int pix = idx / NA;
        int wi = pix % WW;
        int hi = pix / WW;
        g_tboxes[rank] = decode_box(deltas, iminfo, a, pix, wi, hi);
        if ((u32)(mykey >> 32) >= 0x80000000u)
            atomicOr(&g_vbits[rank >> 6], 1ull << (rank & 63));
    }
}

__device__ __forceinline__ bool iou_gt(float4 a, float aa, float4 b, float ab) {
    float xx1 = fmaxf(a.x, b.x), yy1 = fmaxf(a.y, b.y);
    float xx2 = fminf(a.z, b.z), yy2 = fminf(a.w, b.w);
    float ww = fmaxf(xx2 - xx1, 0.f);
    float hh = fmaxf(yy2 - yy1, 0.f);
    float inter = ww * hh;
    return inter > 0.7f * (aa + ab - inter);
}

// Chunked greedy NMS, one block of 512 threads (8 subs per candidate), ~9KB
// static smem, no mask matrix. Copies+zeros g_vbits at entry (self-cleaning).
// Per 64-candidate word: (a) 8 threads/candidate test vs kept set (early
// break), (b) 8 threads/candidate build intra-word pairwise masks, (c) thread
// 0 resolves serially with 64-bit ops. Exact greedy semantics; early exit at
// 300 kept.
__global__ void nms_chunked_kernel(float* __restrict__ out) {
    __shared__ float4 kbox[POST_NMS];
    __shared__ float karea[POST_NMS];
    __shared__ float4 cbox[64];
    __shared__ float carea[64];
    __shared__ u64 cmask[64];
    __shared__ u64 sv[COLB];
    __shared__ u64 s_supp;
    __shared__ int s_kept;

    int tid = threadIdx.x;
    int c = tid >> 3;               // candidate owned by this oct (0..63)
    int sub = tid & 7;

    for (int t = tid; t < POST_NMS * 5; t += 512) out[t] = 0.0f;
    for (int t = tid; t < COLB; t += 512) { sv[t] = g_vbits[t]; g_vbits[t] = 0ull; }
    if (tid == 0) s_kept = 0;
    __syncthreads();

    for (int w = 0; w < COLB; w++) {
        int base = w << 6;
        int nc = min(64, PRE_NMS - base);

        if (tid < 64) {
            float4 b = (tid < nc) ? g_tboxes[base + tid]
                                  : make_float4(0.f, 0.f, 0.f, 0.f);
            cbox[tid] = b;
            carea[tid] = (b.z - b.x) * (b.w - b.y);
            cmask[tid] = 0ull;
        }
        if (tid == 0) s_supp = 0ull;
        __syncthreads();

        float4 bc = cbox[c];
        float ac = carea[c];

        // (a) suppression by already-kept boxes (oct-split, early break)
        int kept = s_kept;
        bool supp = false;
        for (int k = sub; k < kept; k += 8) {
            if (iou_gt(bc, ac, kbox[k], karea[k])) { supp = true; break; }
        }
        if (supp) atomicOr(&s_supp, 1ull << c);

        // (b) intra-word pairwise masks: bits j > c suppressed by c
        u64 m = 0ull;
        for (int j = c + 1 + sub; j < nc; j += 8) {
            if (iou_gt(bc, ac, cbox[j], carea[j])) m |= 1ull << j;
        }
        if (m) atomicOr(&cmask[c], m);
        __syncthreads();

        // (c) serial resolution of this word
        if (tid == 0) {
            u64 alive = sv[w] & ~s_supp;
            if (nc < 64) alive &= (1ull << nc) - 1ull;
            int kk = s_kept;
            while (alive && kk < POST_NMS) {
                int cc = __ffsll(alive) - 1;
                float4 b = cbox[cc];
                kbox[kk] = b;
                karea[kk] = carea[cc];
                float* o = out + kk * 5;
                o[0] = 0.f; o[1] = b.x; o[2] = b.y; o[3] = b.z; o[4] = b.w;
                kk++;
                alive &= ~(1ull << cc);
                alive &= ~cmask[cc];
            }
            s_kept = kk;
        }
        __syncthreads();
        if (s_kept >= POST_NMS) break;
    }
}

// ------------------------------- launch -------------------------------------
extern "C" void kernel_launch(void* const* d_in, const int* in_sizes, int n_in,
                              void* d_out, int out_size) {
    const float* scores = (const float*)d_in[0];
    const float* deltas = (const float*)d_in[1];
    const float* iminfo = (const float*)d_in[2];
    float* out = (float*)d_out;

    decode_kernel<<<(NTOT + 255) / 256, 256>>>(scores, deltas, iminfo);
    pick16_kernel<<<1, 1024>>>();
    compact_kernel<<<(NTOT / 4 + 255) / 256, 256>>>();
    rank_scatter_kernel<<<SEL_CAP / 256, 256>>>(deltas, iminfo);
    nms_chunked_kernel<<<1, 512>>>(out);
}